// round 11
// baseline (speedup 1.0000x reference)
#include <cuda_runtime.h>
#include <math.h>

#define BB 8
#define NN 4096
#define DD 128
#define KT 64
#define RR 512
#define NT 256
#define GRID_N 256

#define OFF_POL     (BB*KT*DD)
#define OFF_SCORER  (OFF_POL + BB)
#define OFF_ENT     (OFF_SCORER + BB*DD)

typedef unsigned long long u64;

__device__ __forceinline__ u64 pk2(float lo, float hi) {
    u64 r; asm("mov.b64 %0,{%1,%2};" : "=l"(r) : "f"(lo), "f"(hi)); return r;
}
__device__ __forceinline__ void up2(u64 v, float& lo, float& hi) {
    asm("mov.b64 {%0,%1},%2;" : "=f"(lo), "=f"(hi) : "l"(v));
}
__device__ __forceinline__ u64 ffma2(u64 a, u64 b, u64 c) {
    u64 d; asm("fma.rn.f32x2 %0,%1,%2,%3;" : "=l"(d) : "l"(a), "l"(b), "l"(c)); return d;
}
__device__ __forceinline__ u64 padd2(u64 a, u64 b) {
    u64 d; asm("add.rn.f32x2 %0,%1,%2;" : "=l"(d) : "l"(a), "l"(b)); return d;
}
__device__ __forceinline__ float sigf(float x) { return 1.f / (1.f + __expf(-x)); }

// Device scratch
__device__ float g_scorer_n[BB*DD];
__device__ float g_scores[BB*NN];
__device__ u64   g_keys[BB*NN];
__device__ float g_z[BB*DD*DD];
__device__ float g_ne[BB*KT*DD];
__device__ float g_A[BB*KT*KT];
__device__ float g_u[BB*DD*DD];
__device__ float g_rq[BB*DD*DD];
__device__ float g_preh[BB*DD*DD];
__device__ float g_newQ[BB*DD*DD];
__device__ float g_P[BB*KT*DD];
__device__ float g_h1[BB*KT*DD];
__device__ float g_G[BB*KT*DD];

// grid barrier state (generation counter survives graph replays)
__device__ volatile unsigned g_bcnt;
__device__ volatile unsigned g_bgen;

__device__ __forceinline__ void gridbar() {
    __syncthreads();
    if (threadIdx.x == 0) {
        unsigned gen = g_bgen;
        __threadfence();
        if (atomicAdd((unsigned*)&g_bcnt, 1u) == GRID_N - 1) {
            g_bcnt = 0;
            __threadfence();
            g_bgen = gen + 1;
        } else {
            while (g_bgen == gen) __nanosleep(32);
        }
        __threadfence();
    }
    __syncthreads();
}

// ---------------------------------------------------------------------------
// Single persistent kernel: 8 phases with software grid barriers.
// ---------------------------------------------------------------------------
__global__ void __launch_bounds__(NT, 2) k_fused(
    const float* __restrict__ Ahat, const float* __restrict__ node_embs,
    const float* __restrict__ ht, const float* __restrict__ prevQ,
    const float* __restrict__ W_map, const float* __restrict__ b_map,
    const float* __restrict__ Wu, const float* __restrict__ Uu, const float* __restrict__ bu,
    const float* __restrict__ Wr, const float* __restrict__ Ur, const float* __restrict__ br,
    const float* __restrict__ Wh, const float* __restrict__ Uh, const float* __restrict__ bh,
    const float* __restrict__ sW, float* __restrict__ out)
{
    extern __shared__ char dyn[];
    const int bid = blockIdx.x, tid = threadIdx.x;
    const int warp = tid >> 5, lane = tid & 31;

    __shared__ float sred[8], sred2[8];
    __shared__ float s_M, s_logZ, s_inv;
    __shared__ int   s_idx[KT];
    __shared__ float s_t[KT], s_v[KT], s_di[KT];
    __shared__ float s_ssc[DD];

    // ================= Phase A: scorer (blocks 0..7) =================
    if (bid < BB) {
        const int b = bid;
        float* sht  = (float*)dyn;                 // 512 floats
        float* part = (float*)(dyn + 2048);        // 2*128 floats
        for (int i = tid; i < RR; i += NT) sht[i] = ht[b*RR + i];
        __syncthreads();
        const int d = tid & 127, rq = tid >> 7;    // rq in 0..1
        float acc = 0.f;
        const int r0 = rq * 256;
        #pragma unroll 4
        for (int r = 0; r < 256; ++r) acc = fmaf(sht[r0 + r], W_map[(r0 + r)*DD + d], acc);
        part[rq*DD + d] = acc;
        __syncthreads();
        if (tid < DD) {
            float s = part[tid] + part[DD + tid] + b_map[tid];
            float sc = tanhf(s);
            s_ssc[tid] = sc;
            out[OFF_SCORER + b*DD + tid] = sc;
        }
        __syncthreads();
        if (tid < 32) {
            float s = 0.f;
            for (int i = tid; i < DD; i += 32) s += s_ssc[i]*s_ssc[i];
            #pragma unroll
            for (int o = 16; o; o >>= 1) s += __shfl_xor_sync(0xffffffffu, s, o);
            if (tid == 0) s_inv = 1.0f / sqrtf(s);
        }
        __syncthreads();
        if (tid < DD) g_scorer_n[b*DD + tid] = s_ssc[tid] * s_inv;
    }
    gridbar();

    // ========== Phase B: scores + bitonic stage-1 (all 256 blocks) ==========
    {
        const int b = bid >> 5, base = (bid & 31) * 128;
        float4* ssc  = (float4*)dyn;               // 32
        float*  sc   = (float*)(dyn + 512);        // 128
        u64*    keys = (u64*)(dyn + 1024);         // 128
        if (tid < 32) ssc[tid] = ((const float4*)(g_scorer_n + b*DD))[tid];
        __syncthreads();
        const float4 sv = ssc[lane];
        #pragma unroll
        for (int t = 0; t < 16; t += 4) {
            const int n0 = base + warp*16 + t;
            float a[4];
            #pragma unroll
            for (int q = 0; q < 4; ++q) {
                const float4 v = ((const float4*)(node_embs + ((size_t)(b*NN + n0 + q))*DD))[lane];
                a[q] = v.x*sv.x + v.y*sv.y + v.z*sv.z + v.w*sv.w;
            }
            #pragma unroll
            for (int o = 16; o; o >>= 1) {
                #pragma unroll
                for (int q = 0; q < 4; ++q) a[q] += __shfl_xor_sync(0xffffffffu, a[q], o);
            }
            if (lane < 4) {
                g_scores[b*NN + n0 + lane] = a[lane];
                sc[warp*16 + t + lane] = a[lane];
            }
        }
        __syncthreads();
        if (tid < 128) {
            const int gi = base + tid;
            float s = sc[tid];
            unsigned u = __float_as_uint(s);
            unsigned m = (u & 0x80000000u) ? ~u : (u | 0x80000000u);
            keys[tid] = ((u64)m << 32) | (unsigned)(NN - 1 - gi);
        }
        __syncthreads();
        for (int k = 2; k <= KT; k <<= 1) {
            for (int j = k >> 1; j > 0; j >>= 1) {
                if (tid < 128) {
                    const int i = tid, l = tid ^ j;
                    if (l > i) {
                        u64 a = keys[i], c = keys[l];
                        bool desc = ((i & k) == 0);
                        if (desc ? (a < c) : (a > c)) { keys[i] = c; keys[l] = a; }
                    }
                }
                __syncthreads();
            }
        }
        if (tid < 128) g_keys[b*NN + base + tid] = keys[tid];
    }
    gridbar();

    // ========== Phase C: softmax stats + stage-2 top-64 + gather (blocks 0..7) ==========
    if (bid < BB) {
        const int b = bid;
        u64* skey = (u64*)dyn;                     // 4096 u64 = 32KB
        float lmax = -INFINITY;
        for (int n = tid; n < NN; n += NT) {
            lmax = fmaxf(lmax, g_scores[b*NN + n]);
            skey[n] = g_keys[b*NN + n];
        }
        #pragma unroll
        for (int o = 16; o; o >>= 1) lmax = fmaxf(lmax, __shfl_xor_sync(0xffffffffu, lmax, o));
        if (lane == 0) sred[warp] = lmax;
        __syncthreads();
        if (tid == 0) { float m = -INFINITY; for (int w = 0; w < 8; ++w) m = fmaxf(m, sred[w]); s_M = m; }
        __syncthreads();
        const float M = s_M;

        float s1 = 0.f, s2 = 0.f;
        for (int n = tid; n < NN; n += NT) {
            float s = g_scores[b*NN + n];
            float e = __expf(s - M);
            s1 += e; s2 = fmaf(s, e, s2);
        }
        #pragma unroll
        for (int o = 16; o; o >>= 1) {
            s1 += __shfl_xor_sync(0xffffffffu, s1, o);
            s2 += __shfl_xor_sync(0xffffffffu, s2, o);
        }
        if (lane == 0) { sred[warp] = s1; sred2[warp] = s2; }
        __syncthreads();
        if (tid == 0) {
            float S1 = 0.f, S2 = 0.f;
            for (int w = 0; w < 8; ++w) { S1 += sred[w]; S2 += sred2[w]; }
            float logZ = M + logf(S1);
            s_logZ = logZ;
            out[OFF_ENT + b] = logZ - S2 / S1;
        }

        // stage 2: halving rounds
        for (int size = NN; size > KT; size >>= 1) {
            const int half = size >> 1;
            __syncthreads();
            u64 tv[8]; int cnt = 0;
            for (int e = tid; e < half; e += NT) {
                int p = e >> 6, t = e & 63;
                u64 a = skey[p*128 + t], c = skey[p*128 + 64 + t];
                tv[cnt++] = (a > c) ? a : c;
            }
            __syncthreads();
            cnt = 0;
            for (int e = tid; e < half; e += NT) skey[e] = tv[cnt++];
            for (int j = 32; j > 0; j >>= 1) {
                __syncthreads();
                for (int i = tid; i < half; i += NT) {
                    const int l = i ^ j;
                    if (l > i) {
                        u64 a = skey[i], c = skey[l];
                        bool desc = ((i & KT) == 0);
                        if (desc ? (a < c) : (a > c)) { skey[i] = c; skey[l] = a; }
                    }
                }
            }
        }
        __syncthreads();

        if (tid < KT) {
            u64 kk = skey[tid];
            int n = NN - 1 - (int)(kk & 0xFFFu);
            unsigned m = (unsigned)(kk >> 32);
            unsigned u = (m & 0x80000000u) ? (m ^ 0x80000000u) : ~m;
            float s = __uint_as_float(u);
            s_idx[tid] = n; s_t[tid] = tanhf(s); s_v[tid] = s;
        }
        __syncthreads();
        if (tid == 0) {
            float sum = 0.f;
            for (int i = 0; i < KT; ++i) sum += s_v[i];
            out[OFF_POL + b] = sum * (1.f/KT) - s_logZ;
        }

        float* sA = (float*)skey;
        for (int e = tid; e < KT*KT; e += NT) {
            int i = e >> 6, j = e & 63;
            sA[e] = Ahat[(size_t)b*NN*NN + (size_t)s_idx[i]*NN + s_idx[j]];
        }
        __syncthreads();
        if (tid < KT) {
            float s = 0.f;
            for (int i = 0; i < KT; ++i) s += sA[i*KT + tid];
            s_di[tid] = 1.0f / sqrtf(s);
        }
        __syncthreads();
        for (int e = tid; e < KT*KT; e += NT) {
            int i = e >> 6, j = e & 63;
            g_A[b*KT*KT + e] = s_di[j] * sA[e] * s_di[i];
        }

        for (int i = warp; i < DD; i += 8) {
            int k = i & (KT - 1);
            const float* e = node_embs + ((size_t)(b*NN + s_idx[k]))*DD;
            float tv2 = s_t[k];
            for (int d = lane; d < DD; d += 32) {
                float val = e[d];
                g_z[((size_t)b*DD + d)*DD + i] = val * tv2;
                if (i < KT) g_ne[(b*KT + i)*DD + d] = val;
            }
        }
    }
    gridbar();

    // ========== Phase D: gates (all 256 blocks; b=bid>>5, x=bid&31) ==========
    {
        u64*    swt = (u64*)dyn;                         // 5*512 u64 (20KB)
        float4* sz  = (float4*)(dyn + 5*512*8);          // 2*512 float4 (16KB)
        float4* sq  = sz + 2*512;                        // 2*512 float4 (16KB)
        const int b = bid >> 5, i0 = (bid & 31)*4;
        const int pr = warp >> 2, g = warp & 3;
        const int rA = pr*2, rB = rA + 1;
        const int giA = i0 + rA, giB = i0 + rB;

        for (int e = tid; e < 512; e += NT) {
            int r = e>>7, k = e&127;
            float a;
            a = Wu[(i0+r)*DD+k]; swt[       e] = pk2(a,a);
            a = Uu[(i0+r)*DD+k]; swt[ 512 + e] = pk2(a,a);
            a = Wr[(i0+r)*DD+k]; swt[1024 + e] = pk2(a,a);
            a = Ur[(i0+r)*DD+k]; swt[1536 + e] = pk2(a,a);
            a = Wh[(i0+r)*DD+k]; swt[2048 + e] = pk2(a,a);
        }
        const float* z = g_z + (size_t)b*DD*DD;
        const float* Q = prevQ + (size_t)b*DD*DD;

        float4 rz[2], rqv[2];
        #pragma unroll
        for (int p = 0; p < 2; ++p) {
            int e = tid + 256*p;
            rz[p]  = ((const float4*)(z + (size_t)(e>>5)*DD))[e&31];
            rqv[p] = ((const float4*)(Q + (size_t)(e>>5)*DD))[e&31];
        }
        #pragma unroll
        for (int p = 0; p < 2; ++p) { int e = tid+256*p; sz[e]=rz[p]; sq[e]=rqv[p]; }
        __syncthreads();

        u64 auA0=0,auA1=0,arA0=0,arA1=0,ahA0=0,ahA1=0;
        u64 auB0=0,auB1=0,arB0=0,arB1=0,ahB0=0,ahB1=0;
        if (g == 0) {
            float4 v;
            v = *(const float4*)&bu[giA*DD + 4*lane]; auA0=pk2(v.x,v.y); auA1=pk2(v.z,v.w);
            v = *(const float4*)&br[giA*DD + 4*lane]; arA0=pk2(v.x,v.y); arA1=pk2(v.z,v.w);
            v = *(const float4*)&bh[giA*DD + 4*lane]; ahA0=pk2(v.x,v.y); ahA1=pk2(v.z,v.w);
            v = *(const float4*)&bu[giB*DD + 4*lane]; auB0=pk2(v.x,v.y); auB1=pk2(v.z,v.w);
            v = *(const float4*)&br[giB*DD + 4*lane]; arB0=pk2(v.x,v.y); arB1=pk2(v.z,v.w);
            v = *(const float4*)&bh[giB*DD + 4*lane]; ahB0=pk2(v.x,v.y); ahB1=pk2(v.z,v.w);
        }

        for (int c = 0; c < 8; ++c) {
            const int cb = c & 1, nb = cb ^ 1;
            if (c < 7) {
                #pragma unroll
                for (int p = 0; p < 2; ++p) {
                    int e = tid + 256*p;
                    int r16 = (c+1)*16 + (e>>5);
                    rz[p]  = ((const float4*)(z + (size_t)r16*DD))[e&31];
                    rqv[p] = ((const float4*)(Q + (size_t)r16*DD))[e&31];
                }
            }
            const ulonglong2* zz = (const ulonglong2*)(sz + cb*512);
            const ulonglong2* qq = (const ulonglong2*)(sq + cb*512);
            const int kb = c*16 + g*4;
            const u64* pA = swt + rA*128 + kb;
            const u64* pB = swt + rB*128 + kb;
            #pragma unroll
            for (int q = 0; q < 4; ++q) {
                ulonglong2 zv = zz[(g*4+q)*32 + lane];
                ulonglong2 qv = qq[(g*4+q)*32 + lane];
                u64 wuA=pA[q], uuA=pA[512+q], wrA=pA[1024+q], urA=pA[1536+q], whA=pA[2048+q];
                u64 wuB=pB[q], uuB=pB[512+q], wrB=pB[1024+q], urB=pB[1536+q], whB=pB[2048+q];
                auA0=ffma2(wuA,zv.x,auA0); auA1=ffma2(wuA,zv.y,auA1);
                auA0=ffma2(uuA,qv.x,auA0); auA1=ffma2(uuA,qv.y,auA1);
                arA0=ffma2(wrA,zv.x,arA0); arA1=ffma2(wrA,zv.y,arA1);
                arA0=ffma2(urA,qv.x,arA0); arA1=ffma2(urA,qv.y,arA1);
                ahA0=ffma2(whA,zv.x,ahA0); ahA1=ffma2(whA,zv.y,ahA1);
                auB0=ffma2(wuB,zv.x,auB0); auB1=ffma2(wuB,zv.y,auB1);
                auB0=ffma2(uuB,qv.x,auB0); auB1=ffma2(uuB,qv.y,auB1);
                arB0=ffma2(wrB,zv.x,arB0); arB1=ffma2(wrB,zv.y,arB1);
                arB0=ffma2(urB,qv.x,arB0); arB1=ffma2(urB,qv.y,arB1);
                ahB0=ffma2(whB,zv.x,ahB0); ahB1=ffma2(whB,zv.y,ahB1);
            }
            if (c < 7) {
                #pragma unroll
                for (int p = 0; p < 2; ++p) { int e = tid+256*p; sz[nb*512+e]=rz[p]; sq[nb*512+e]=rqv[p]; }
            }
            __syncthreads();
        }

        u64* sp = (u64*)sz;
        if (g > 0) {
            int base = (pr*36 + (g-1)*12)*32 + lane;
            sp[base+0*32]=auA0;  sp[base+1*32]=auA1;  sp[base+2*32]=arA0;  sp[base+3*32]=arA1;
            sp[base+4*32]=ahA0;  sp[base+5*32]=ahA1;  sp[base+6*32]=auB0;  sp[base+7*32]=auB1;
            sp[base+8*32]=arB0;  sp[base+9*32]=arB1;  sp[base+10*32]=ahB0; sp[base+11*32]=ahB1;
        }
        __syncthreads();
        if (g == 0) {
            #pragma unroll
            for (int gi = 0; gi < 3; ++gi) {
                int base = (pr*36 + gi*12)*32 + lane;
                auA0=padd2(auA0,sp[base+0*32]);  auA1=padd2(auA1,sp[base+1*32]);
                arA0=padd2(arA0,sp[base+2*32]);  arA1=padd2(arA1,sp[base+3*32]);
                ahA0=padd2(ahA0,sp[base+4*32]);  ahA1=padd2(ahA1,sp[base+5*32]);
                auB0=padd2(auB0,sp[base+6*32]);  auB1=padd2(auB1,sp[base+7*32]);
                arB0=padd2(arB0,sp[base+8*32]);  arB1=padd2(arB1,sp[base+9*32]);
                ahB0=padd2(ahB0,sp[base+10*32]); ahB1=padd2(ahB1,sp[base+11*32]);
            }
            float f0,f1,f2,f3;
            {
                const size_t o = ((size_t)b*DD + giA)*DD + 4*lane;
                up2(auA0,f0,f1); up2(auA1,f2,f3);
                *(float4*)&g_u[o] = make_float4(sigf(f0),sigf(f1),sigf(f2),sigf(f3));
                up2(arA0,f0,f1); up2(arA1,f2,f3);
                float4 q4 = *(const float4*)&Q[(size_t)giA*DD + 4*lane];
                *(float4*)&g_rq[o] = make_float4(sigf(f0)*q4.x, sigf(f1)*q4.y, sigf(f2)*q4.z, sigf(f3)*q4.w);
                up2(ahA0,f0,f1); up2(ahA1,f2,f3);
                *(float4*)&g_preh[o] = make_float4(f0,f1,f2,f3);
            }
            {
                const size_t o = ((size_t)b*DD + giB)*DD + 4*lane;
                up2(auB0,f0,f1); up2(auB1,f2,f3);
                *(float4*)&g_u[o] = make_float4(sigf(f0),sigf(f1),sigf(f2),sigf(f3));
                up2(arB0,f0,f1); up2(arB1,f2,f3);
                float4 q4 = *(const float4*)&Q[(size_t)giB*DD + 4*lane];
                *(float4*)&g_rq[o] = make_float4(sigf(f0)*q4.x, sigf(f1)*q4.y, sigf(f2)*q4.z, sigf(f3)*q4.w);
                up2(ahB0,f0,f1); up2(ahB1,f2,f3);
                *(float4*)&g_preh[o] = make_float4(f0,f1,f2,f3);
            }
        }
    }
    gridbar();

    // ========== Phase E: newQ (all 256 blocks) ==========
    {
        u64*    swt = (u64*)dyn;                          // 512 u64 (4KB)
        float4* sb  = (float4*)(dyn + 4096);              // 2*512 float4 (16KB)
        u64*    sp  = (u64*)(dyn + 4096 + 16384);         // 768 u64 (6KB)
        const int b = bid >> 5, i0 = (bid & 31)*4;
        const int pr = warp >> 2, g = warp & 3;
        const int rA = pr*2, rB = rA + 1;
        const int giA = i0 + rA, giB = i0 + rB;
        for (int e = tid; e < 512; e += NT) {
            float a = Uh[(i0 + (e>>7))*DD + (e&127)]; swt[e] = pk2(a,a);
        }
        const float* Bm = g_rq + (size_t)b*DD*DD;
        float4 rb[2];
        #pragma unroll
        for (int p = 0; p < 2; ++p) { int e = tid+256*p; rb[p] = ((const float4*)(Bm + (size_t)(e>>5)*DD))[e&31]; }
        #pragma unroll
        for (int p = 0; p < 2; ++p) { int e = tid+256*p; sb[e]=rb[p]; }
        __syncthreads();
        u64 aA0=0,aA1=0,aB0=0,aB1=0;
        for (int c = 0; c < 8; ++c) {
            const int cb = c & 1, nb = cb ^ 1;
            if (c < 7) {
                #pragma unroll
                for (int p = 0; p < 2; ++p) {
                    int e = tid + 256*p;
                    rb[p] = ((const float4*)(Bm + (size_t)((c+1)*16 + (e>>5))*DD))[e&31];
                }
            }
            const ulonglong2* bb = (const ulonglong2*)(sb + cb*512);
            const u64* pA = swt + rA*128 + c*16 + g*4;
            const u64* pB = swt + rB*128 + c*16 + g*4;
            #pragma unroll
            for (int q = 0; q < 4; ++q) {
                ulonglong2 bv = bb[(g*4+q)*32 + lane];
                u64 wtA = pA[q], wtB = pB[q];
                aA0 = ffma2(wtA, bv.x, aA0); aA1 = ffma2(wtA, bv.y, aA1);
                aB0 = ffma2(wtB, bv.x, aB0); aB1 = ffma2(wtB, bv.y, aB1);
            }
            if (c < 7) {
                #pragma unroll
                for (int p = 0; p < 2; ++p) { int e = tid+256*p; sb[nb*512+e]=rb[p]; }
            }
            __syncthreads();
        }
        if (g > 0) {
            int base = (pr*12 + (g-1)*4)*32 + lane;
            sp[base] = aA0; sp[base+32] = aA1; sp[base+64] = aB0; sp[base+96] = aB1;
        }
        __syncthreads();
        if (g == 0) {
            #pragma unroll
            for (int gi = 0; gi < 3; ++gi) {
                int base = (pr*12 + gi*4)*32 + lane;
                aA0 = padd2(aA0, sp[base]);    aA1 = padd2(aA1, sp[base+32]);
                aB0 = padd2(aB0, sp[base+64]); aB1 = padd2(aB1, sp[base+96]);
            }
            float f0,f1,f2,f3;
            {
                up2(aA0,f0,f1); up2(aA1,f2,f3);
                const size_t o = ((size_t)b*DD + giA)*DD + 4*lane;
                float4 ph = *(const float4*)&g_preh[o];
                float4 uv = *(const float4*)&g_u[o];
                float4 q4 = *(const float4*)&prevQ[(size_t)b*DD*DD + giA*DD + 4*lane];
                float h0 = tanhf(f0+ph.x), h1 = tanhf(f1+ph.y), h2 = tanhf(f2+ph.z), h3 = tanhf(f3+ph.w);
                *(float4*)&g_newQ[o] = make_float4(
                    (1.f-uv.x)*q4.x + uv.x*h0, (1.f-uv.y)*q4.y + uv.y*h1,
                    (1.f-uv.z)*q4.z + uv.z*h2, (1.f-uv.w)*q4.w + uv.w*h3);
            }
            {
                up2(aB0,f0,f1); up2(aB1,f2,f3);
                const size_t o = ((size_t)b*DD + giB)*DD + 4*lane;
                float4 ph = *(const float4*)&g_preh[o];
                float4 uv = *(const float4*)&g_u[o];
                float4 q4 = *(const float4*)&prevQ[(size_t)b*DD*DD + giB*DD + 4*lane];
                float h0 = tanhf(f0+ph.x), h1 = tanhf(f1+ph.y), h2 = tanhf(f2+ph.z), h3 = tanhf(f3+ph.w);
                *(float4*)&g_newQ[o] = make_float4(
                    (1.f-uv.x)*q4.x + uv.x*h0, (1.f-uv.y)*q4.y + uv.y*h1,
                    (1.f-uv.z)*q4.z + uv.z*h2, (1.f-uv.w)*q4.w + uv.w*h3);
            }
        }
    }
    gridbar();

    // ========== Phase F: P = ne @ newQ (blocks 0..127) ==========
    if (bid < 128) {
        u64*    swt = (u64*)dyn;
        float4* sb  = (float4*)(dyn + 4096);
        u64*    sp  = (u64*)(dyn + 4096 + 16384);
        const int b = bid >> 4, i0 = (bid & 15)*4;
        const int pr = warp >> 2, g = warp & 3;
        const int rA = pr*2, rB = rA + 1;
        const int giA = i0 + rA, giB = i0 + rB;
        for (int e = tid; e < 512; e += NT) {
            float a = g_ne[((size_t)b*KT + i0 + (e>>7))*DD + (e&127)]; swt[e] = pk2(a,a);
        }
        const float* Bm = g_newQ + (size_t)b*DD*DD;
        float4 rb[2];
        #pragma unroll
        for (int p = 0; p < 2; ++p) { int e = tid+256*p; rb[p] = ((const float4*)(Bm + (size_t)(e>>5)*DD))[e&31]; }
        #pragma unroll
        for (int p = 0; p < 2; ++p) { int e = tid+256*p; sb[e]=rb[p]; }
        __syncthreads();
        u64 aA0=0,aA1=0,aB0=0,aB1=0;
        for (int c = 0; c < 8; ++c) {
            const int cb = c & 1, nb = cb ^ 1;
            if (c < 7) {
                #pragma unroll
                for (int p = 0; p < 2; ++p) {
                    int e = tid + 256*p;
                    rb[p] = ((const float4*)(Bm + (size_t)((c+1)*16 + (e>>5))*DD))[e&31];
                }
            }
            const ulonglong2* bb = (const ulonglong2*)(sb + cb*512);
            const u64* pA = swt + rA*128 + c*16 + g*4;
            const u64* pB = swt + rB*128 + c*16 + g*4;
            #pragma unroll
            for (int q = 0; q < 4; ++q) {
                ulonglong2 bv = bb[(g*4+q)*32 + lane];
                u64 wtA = pA[q], wtB = pB[q];
                aA0 = ffma2(wtA, bv.x, aA0); aA1 = ffma2(wtA, bv.y, aA1);
                aB0 = ffma2(wtB, bv.x, aB0); aB1 = ffma2(wtB, bv.y, aB1);
            }
            if (c < 7) {
                #pragma unroll
                for (int p = 0; p < 2; ++p) { int e = tid+256*p; sb[nb*512+e]=rb[p]; }
            }
            __syncthreads();
        }
        if (g > 0) {
            int base = (pr*12 + (g-1)*4)*32 + lane;
            sp[base] = aA0; sp[base+32] = aA1; sp[base+64] = aB0; sp[base+96] = aB1;
        }
        __syncthreads();
        if (g == 0) {
            #pragma unroll
            for (int gi = 0; gi < 3; ++gi) {
                int base = (pr*12 + gi*4)*32 + lane;
                aA0 = padd2(aA0, sp[base]);    aA1 = padd2(aA1, sp[base+32]);
                aB0 = padd2(aB0, sp[base+64]); aB1 = padd2(aB1, sp[base+96]);
            }
            float f0,f1,f2,f3;
            up2(aA0,f0,f1); up2(aA1,f2,f3);
            *(float4*)&g_P[((size_t)b*KT + giA)*DD + 4*lane] = make_float4(f0,f1,f2,f3);
            up2(aB0,f0,f1); up2(aB1,f2,f3);
            *(float4*)&g_P[((size_t)b*KT + giB)*DD + 4*lane] = make_float4(f0,f1,f2,f3);
        }
    }
    gridbar();

    // ========== Phase G: h1 = relu(A@P); G = h1@sW (blocks 0..127) ==========
    if (bid < 128) {
        float* buf  = (float*)dyn;                        // 32KB
        u64*   sAW  = (u64*)(dyn + 32768);                // 2KB
        u64*   sh1p = (u64*)(dyn + 32768 + 2048);         // 4KB
        u64*   sp   = (u64*)(dyn + 32768 + 2048 + 4096);  // 6KB
        const int b = bid >> 4, i0 = (bid & 15)*4;
        const int pr = warp >> 2, g = warp & 3;
        const int rA = pr*2, rB = rA + 1;
        const int giA = i0 + rA, giB = i0 + rB;
        for (int e = tid; e < 4*KT; e += NT) {
            float a = g_A[b*KT*KT + (i0 + (e>>6))*KT + (e&63)]; sAW[e] = pk2(a,a);
        }
        float4* bf4 = (float4*)buf;
        const float4* Psrc = (const float4*)(g_P + (size_t)b*KT*DD);
        for (int e = tid; e < 2048; e += NT) bf4[e] = Psrc[e];
        __syncthreads();

        u64 aA0=0,aA1=0,aB0=0,aB1=0;
        {
            const ulonglong2* bb = (const ulonglong2*)buf;
            const u64* pA = sAW + rA*KT + g*16;
            const u64* pB = sAW + rB*KT + g*16;
            #pragma unroll
            for (int q = 0; q < 16; ++q) {
                ulonglong2 bv = bb[(g*16+q)*32 + lane];
                u64 wtA = pA[q], wtB = pB[q];
                aA0 = ffma2(wtA, bv.x, aA0); aA1 = ffma2(wtA, bv.y, aA1);
                aB0 = ffma2(wtB, bv.x, aB0); aB1 = ffma2(wtB, bv.y, aB1);
            }
        }
        __syncthreads();
        if (g > 0) {
            int base = (pr*12 + (g-1)*4)*32 + lane;
            sp[base] = aA0; sp[base+32] = aA1; sp[base+64] = aB0; sp[base+96] = aB1;
        }
        __syncthreads();
        if (g == 0) {
            #pragma unroll
            for (int gi = 0; gi < 3; ++gi) {
                int base = (pr*12 + gi*4)*32 + lane;
                aA0 = padd2(aA0, sp[base]);    aA1 = padd2(aA1, sp[base+32]);
                aB0 = padd2(aB0, sp[base+64]); aB1 = padd2(aB1, sp[base+96]);
            }
            float f0,f1,f2,f3;
            up2(aA0,f0,f1); up2(aA1,f2,f3);
            f0=fmaxf(f0,0.f); f1=fmaxf(f1,0.f); f2=fmaxf(f2,0.f); f3=fmaxf(f3,0.f);
            *(float4*)&g_h1[((size_t)b*KT + giA)*DD + 4*lane] = make_float4(f0,f1,f2,f3);
            sh1p[rA*DD + 4*lane+0]=pk2(f0,f0); sh1p[rA*DD + 4*lane+1]=pk2(f1,f1);
            sh1p[rA*DD + 4*lane+2]=pk2(f2,f2); sh1p[rA*DD + 4*lane+3]=pk2(f3,f3);
            up2(aB0,f0,f1); up2(aB1,f2,f3);
            f0=fmaxf(f0,0.f); f1=fmaxf(f1,0.f); f2=fmaxf(f2,0.f); f3=fmaxf(f3,0.f);
            *(float4*)&g_h1[((size_t)b*KT + giB)*DD + 4*lane] = make_float4(f0,f1,f2,f3);
            sh1p[rB*DD + 4*lane+0]=pk2(f0,f0); sh1p[rB*DD + 4*lane+1]=pk2(f1,f1);
            sh1p[rB*DD + 4*lane+2]=pk2(f2,f2); sh1p[rB*DD + 4*lane+3]=pk2(f3,f3);
        }
        __syncthreads();

        float4 rb[4];
        #pragma unroll
        for (int p = 0; p < 4; ++p) {
            int e = tid + 256*p;
            rb[p] = ((const float4*)(sW + (size_t)(e>>5)*DD))[e&31];
        }
        #pragma unroll
        for (int p = 0; p < 4; ++p) { int e = tid+256*p; bf4[e] = rb[p]; }
        __syncthreads();
        u64 gA0=0,gA1=0,gB0=0,gB1=0;
        for (int c = 0; c < 4; ++c) {
            const int cb = c & 1, nb = cb ^ 1;
            if (c < 3) {
                #pragma unroll
                for (int p = 0; p < 4; ++p) {
                    int e = tid + 256*p;
                    rb[p] = ((const float4*)(sW + (size_t)((c+1)*32 + (e>>5))*DD))[e&31];
                }
            }
            const ulonglong2* bb = (const ulonglong2*)(buf + cb*4096);
            const u64* hA = sh1p + rA*DD + c*32 + g*8;
            const u64* hB = sh1p + rB*DD + c*32 + g*8;
            #pragma unroll
            for (int q = 0; q < 8; ++q) {
                ulonglong2 bv = bb[(g*8+q)*32 + lane];
                u64 wtA = hA[q], wtB = hB[q];
                gA0 = ffma2(wtA, bv.x, gA0); gA1 = ffma2(wtA, bv.y, gA1);
                gB0 = ffma2(wtB, bv.x, gB0); gB1 = ffma2(wtB, bv.y, gB1);
            }
            if (c < 3) {
                #pragma unroll
                for (int p = 0; p < 4; ++p) { int e = tid+256*p; bf4[nb*1024 + e] = rb[p]; }
            }
            __syncthreads();
        }
        if (g > 0) {
            int base = (pr*12 + (g-1)*4)*32 + lane;
            sp[base] = gA0; sp[base+32] = gA1; sp[base+64] = gB0; sp[base+96] = gB1;
        }
        __syncthreads();
        if (g == 0) {
            #pragma unroll
            for (int gi = 0; gi < 3; ++gi) {
                int base = (pr*12 + gi*4)*32 + lane;
                gA0 = padd2(gA0, sp[base]);    gA1 = padd2(gA1, sp[base+32]);
                gB0 = padd2(gB0, sp[base+64]); gB1 = padd2(gB1, sp[base+96]);
            }
            float f0,f1,f2,f3;
            up2(gA0,f0,f1); up2(gA1,f2,f3);
            *(float4*)&g_G[((size_t)b*KT + giA)*DD + 4*lane] = make_float4(f0,f1,f2,f3);
            up2(gB0,f0,f1); up2(gB1,f2,f3);
            *(float4*)&g_G[((size_t)b*KT + giB)*DD + 4*lane] = make_float4(f0,f1,f2,f3);
        }
    }
    gridbar();

    // ========== Phase H: out = (h1 + relu(A@G))/2 (blocks 0..127) ==========
    if (bid < 128) {
        float* buf = (float*)dyn;                   // 32KB
        u64*   sAW = (u64*)(dyn + 32768);           // 2KB
        u64*   sp  = (u64*)(dyn + 32768 + 2048);    // 6KB
        const int b = bid >> 4, i0 = (bid & 15)*4;
        const int pr = warp >> 2, g = warp & 3;
        const int rA = pr*2, rB = rA + 1;
        const int giA = i0 + rA, giB = i0 + rB;
        for (int e = tid; e < 4*KT; e += NT) {
            float a = g_A[b*KT*KT + (i0 + (e>>6))*KT + (e&63)]; sAW[e] = pk2(a,a);
        }
        float4* bf4 = (float4*)buf;
        const float4* Gsrc = (const float4*)(g_G + (size_t)b*KT*DD);
        for (int e = tid; e < 2048; e += NT) bf4[e] = Gsrc[e];
        __syncthreads();
        u64 aA0=0,aA1=0,aB0=0,aB1=0;
        const ulonglong2* bb = (const ulonglong2*)buf;
        const u64* pA = sAW + rA*KT + g*16;
        const u64* pB = sAW + rB*KT + g*16;
        #pragma unroll
        for (int q = 0; q < 16; ++q) {
            ulonglong2 bv = bb[(g*16+q)*32 + lane];
            u64 wtA = pA[q], wtB = pB[q];
            aA0 = ffma2(wtA, bv.x, aA0); aA1 = ffma2(wtA, bv.y, aA1);
            aB0 = ffma2(wtB, bv.x, aB0); aB1 = ffma2(wtB, bv.y, aB1);
        }
        if (g > 0) {
            int base = (pr*12 + (g-1)*4)*32 + lane;
            sp[base] = aA0; sp[base+32] = aA1; sp[base+64] = aB0; sp[base+96] = aB1;
        }
        __syncthreads();
        if (g == 0) {
            #pragma unroll
            for (int gi = 0; gi < 3; ++gi) {
                int base = (pr*12 + gi*4)*32 + lane;
                aA0 = padd2(aA0, sp[base]);    aA1 = padd2(aA1, sp[base+32]);
                aB0 = padd2(aB0, sp[base+64]); aB1 = padd2(aB1, sp[base+96]);
            }
            float f0,f1,f2,f3;
            up2(aA0,f0,f1); up2(aA1,f2,f3);
            {
                float4 h1v = *(const float4*)&g_h1[((size_t)b*KT + giA)*DD + 4*lane];
                *(float4*)&out[((size_t)b*KT + giA)*DD + 4*lane] = make_float4(
                    (h1v.x + fmaxf(f0,0.f))*0.5f, (h1v.y + fmaxf(f1,0.f))*0.5f,
                    (h1v.z + fmaxf(f2,0.f))*0.5f, (h1v.w + fmaxf(f3,0.f))*0.5f);
            }
            up2(aB0,f0,f1); up2(aB1,f2,f3);
            {
                float4 h1v = *(const float4*)&g_h1[((size_t)b*KT + giB)*DD + 4*lane];
                *(float4*)&out[((size_t)b*KT + giB)*DD + 4*lane] = make_float4(
                    (h1v.x + fmaxf(f0,0.f))*0.5f, (h1v.y + fmaxf(f1,0.f))*0.5f,
                    (h1v.z + fmaxf(f2,0.f))*0.5f, (h1v.w + fmaxf(f3,0.f))*0.5f);
            }
        }
    }
}

// ---------------------------------------------------------------------------
extern "C" void kernel_launch(void* const* d_in, const int* in_sizes, int n_in,
                              void* d_out, int out_size)
{
    const float* Ahat      = (const float*)d_in[0];
    const float* node_embs = (const float*)d_in[1];
    const float* ht        = (const float*)d_in[3];
    const float* prevQ     = (const float*)d_in[4];
    const float* W_map     = (const float*)d_in[5];
    const float* b_map     = (const float*)d_in[6];
    const float* Wu        = (const float*)d_in[7];
    const float* Uu        = (const float*)d_in[8];
    const float* bu        = (const float*)d_in[9];
    const float* Wr        = (const float*)d_in[10];
    const float* Ur        = (const float*)d_in[11];
    const float* br        = (const float*)d_in[12];
    const float* Wh        = (const float*)d_in[13];
    const float* Uh        = (const float*)d_in[14];
    const float* bh        = (const float*)d_in[15];
    const float* sW        = (const float*)d_in[16];
    float* out = (float*)d_out;

    const int smem = 53248;
    cudaFuncSetAttribute(k_fused, cudaFuncAttributeMaxDynamicSharedMemorySize, smem);
    k_fused<<<GRID_N, NT, smem>>>(Ahat, node_embs, ht, prevQ, W_map, b_map,
                                  Wu, Uu, bu, Wr, Ur, br, Wh, Uh, bh, sW, out);
}

// round 12
// speedup vs baseline: 1.3406x; 1.3406x over previous
#include <cuda_runtime.h>
#include <math.h>

#define BB 8
#define NN 4096
#define DD 128
#define KT 64
#define RR 512
#define NK 2048   // keys entering stage-2 (after fused first halving round)

#define OFF_POL     (BB*KT*DD)
#define OFF_SCORER  (OFF_POL + BB)
#define OFF_ENT     (OFF_SCORER + BB*DD)

typedef unsigned long long u64;

__device__ __forceinline__ u64 pk2(float lo, float hi) {
    u64 r; asm("mov.b64 %0,{%1,%2};" : "=l"(r) : "f"(lo), "f"(hi)); return r;
}
__device__ __forceinline__ void up2(u64 v, float& lo, float& hi) {
    asm("mov.b64 {%0,%1},%2;" : "=f"(lo), "=f"(hi) : "l"(v));
}
__device__ __forceinline__ u64 ffma2(u64 a, u64 b, u64 c) {
    u64 d; asm("fma.rn.f32x2 %0,%1,%2,%3;" : "=l"(d) : "l"(a), "l"(b), "l"(c)); return d;
}
__device__ __forceinline__ u64 padd2(u64 a, u64 b) {
    u64 d; asm("add.rn.f32x2 %0,%1,%2;" : "=l"(d) : "l"(a), "l"(b)); return d;
}
__device__ __forceinline__ float sigf(float x) { return 1.f / (1.f + __expf(-x)); }

// Device scratch
__device__ float g_scorer_n[BB*DD];
__device__ float g_scores[BB*NN];
__device__ u64   g_keys[BB*NK];
__device__ float g_z[BB*DD*DD];
__device__ float g_ne[BB*KT*DD];
__device__ float g_A[BB*KT*KT];
__device__ float g_u[BB*DD*DD];
__device__ float g_rq[BB*DD*DD];
__device__ float g_preh[BB*DD*DD];
__device__ float g_newQ[BB*DD*DD];
__device__ float g_P[BB*KT*DD];
__device__ float g_h1[BB*KT*DD];
__device__ float g_G[BB*KT*DD];

// ---------------------------------------------------------------------------
// K1: scorer
// ---------------------------------------------------------------------------
__global__ void __launch_bounds__(512) k_scorer(
    const float* __restrict__ ht, const float* __restrict__ W_map,
    const float* __restrict__ b_map, float* __restrict__ out)
{
    const int b = blockIdx.x, tid = threadIdx.x;
    __shared__ float sht[RR];
    __shared__ float part[4][DD];
    __shared__ float ssc[DD];
    __shared__ float s_inv;
    sht[tid] = ht[b*RR + tid];
    __syncthreads();
    const int d = tid & 127, rq = tid >> 7;
    float acc = 0.f;
    const int r0 = rq * 128;
    #pragma unroll 4
    for (int r = 0; r < 128; ++r) acc = fmaf(sht[r0 + r], W_map[(r0 + r)*DD + d], acc);
    part[rq][d] = acc;
    __syncthreads();
    if (tid < DD) {
        float s = part[0][tid] + part[1][tid] + part[2][tid] + part[3][tid] + b_map[tid];
        float sc = tanhf(s);
        ssc[tid] = sc;
        out[OFF_SCORER + b*DD + tid] = sc;
    }
    __syncthreads();
    if (tid < 32) {
        float s = 0.f;
        for (int i = tid; i < DD; i += 32) s += ssc[i]*ssc[i];
        #pragma unroll
        for (int o = 16; o; o >>= 1) s += __shfl_xor_sync(0xffffffffu, s, o);
        if (tid == 0) s_inv = 1.0f / sqrtf(s);
    }
    __syncthreads();
    if (tid < DD) g_scorer_n[b*DD + tid] = ssc[tid] * s_inv;
}

// ---------------------------------------------------------------------------
// K2: scores + bitonic stage-1 + fused first halving round (128 -> top 64)
// Emits one sorted 64-block per scores-block; direction desc iff (bid&1)==0,
// exactly matching stage-2's alternating-block invariant.
// ---------------------------------------------------------------------------
__global__ void __launch_bounds__(128) k_scores(const float* __restrict__ node_embs)
{
    const int b = blockIdx.y, bx = blockIdx.x, base = bx * 128, tid = threadIdx.x;
    const int warp = tid >> 5, lane = tid & 31;
    __shared__ float4 ssc[32];
    __shared__ float sc[128];
    __shared__ u64 keys[128];
    if (tid < 32) ssc[tid] = ((const float4*)(g_scorer_n + b*DD))[tid];
    __syncthreads();
    const float4 sv = ssc[lane];
    #pragma unroll
    for (int t = 0; t < 32; t += 4) {
        const int n0 = base + warp * 32 + t;
        float a[4];
        #pragma unroll
        for (int q = 0; q < 4; ++q) {
            const float4 v = ((const float4*)(node_embs + ((size_t)(b*NN + n0 + q))*DD))[lane];
            a[q] = v.x*sv.x + v.y*sv.y + v.z*sv.z + v.w*sv.w;
        }
        #pragma unroll
        for (int o = 16; o; o >>= 1) {
            #pragma unroll
            for (int q = 0; q < 4; ++q) a[q] += __shfl_xor_sync(0xffffffffu, a[q], o);
        }
        if (lane < 4) {
            g_scores[b*NN + n0 + lane] = a[lane];
            sc[warp*32 + t + lane] = a[lane];
        }
    }
    __syncthreads();
    {
        const int gi = base + tid;
        float s = sc[tid];
        unsigned u = __float_as_uint(s);
        unsigned m = (u & 0x80000000u) ? ~u : (u | 0x80000000u);
        keys[tid] = ((u64)m << 32) | (unsigned)(NN - 1 - gi);
    }
    __syncthreads();
    // stage-1: sort each 64-block; desc iff (local index & k)==0 (matches global)
    for (int k = 2; k <= KT; k <<= 1) {
        for (int j = k >> 1; j > 0; j >>= 1) {
            const int i = tid, l = tid ^ j;
            if (l > i) {
                u64 a = keys[i], c = keys[l];
                bool desc = ((i & k) == 0);
                if (desc ? (a < c) : (a > c)) { keys[i] = c; keys[l] = a; }
            }
            __syncthreads();
        }
    }
    // fused first halving round: max-compact (desc,asc) pair -> bitonic 64,
    // then merge sorted, direction desc iff (bid & 1)==0
    u64 mx;
    if (tid < 64) {
        u64 a = keys[tid], c = keys[64 + tid];
        mx = (a > c) ? a : c;
    }
    __syncthreads();
    if (tid < 64) keys[tid] = mx;
    const bool descB = ((bx & 1) == 0);
    for (int j = 32; j > 0; j >>= 1) {
        __syncthreads();
        if (tid < 64) {
            const int i = tid, l = tid ^ j;
            if (l > i) {
                u64 a = keys[i], c = keys[l];
                if (descB ? (a < c) : (a > c)) { keys[i] = c; keys[l] = a; }
            }
        }
    }
    __syncthreads();
    if (tid < 64) g_keys[b*NK + bx*64 + tid] = keys[tid];
}

// ---------------------------------------------------------------------------
// K3: softmax stats + bitonic stage-2 (from 2048) + gather (A, z, ne)
// ---------------------------------------------------------------------------
__global__ void __launch_bounds__(512) k_topk_gather(
    const float* __restrict__ node_embs, const float* __restrict__ Ahat,
    float* __restrict__ out)
{
    extern __shared__ unsigned long long skey[];   // 2048 u64 = 16KB (reused as sA 16KB)
    const int b = blockIdx.x, tid = threadIdx.x;
    const int warp = tid >> 5, lane = tid & 31;
    __shared__ float sred[16], sred2[16];
    __shared__ float s_M, s_logZ;
    __shared__ int   s_idx[KT];
    __shared__ float s_t[KT];
    __shared__ float s_v[KT];
    __shared__ float s_di[KT];

    for (int n = tid; n < NK; n += 512) skey[n] = g_keys[b*NK + n];

    float lmax = -INFINITY;
    for (int n = tid; n < NN; n += 512) lmax = fmaxf(lmax, g_scores[b*NN + n]);
    #pragma unroll
    for (int o = 16; o; o >>= 1) lmax = fmaxf(lmax, __shfl_xor_sync(0xffffffffu, lmax, o));
    if (lane == 0) sred[warp] = lmax;
    __syncthreads();
    if (tid == 0) { float m = -INFINITY; for (int w = 0; w < 16; ++w) m = fmaxf(m, sred[w]); s_M = m; }
    __syncthreads();
    const float M = s_M;

    float s1 = 0.f, s2 = 0.f;
    for (int n = tid; n < NN; n += 512) {
        float s = g_scores[b*NN + n];
        float e = __expf(s - M);
        s1 += e; s2 = fmaf(s, e, s2);
    }
    #pragma unroll
    for (int o = 16; o; o >>= 1) {
        s1 += __shfl_xor_sync(0xffffffffu, s1, o);
        s2 += __shfl_xor_sync(0xffffffffu, s2, o);
    }
    if (lane == 0) { sred[warp] = s1; sred2[warp] = s2; }
    __syncthreads();
    if (tid == 0) {
        float S1 = 0.f, S2 = 0.f;
        for (int w = 0; w < 16; ++w) { S1 += sred[w]; S2 += sred2[w]; }
        float logZ = M + logf(S1);
        s_logZ = logZ;
        out[OFF_ENT + b] = logZ - S2 / S1;
    }

    // stage-2: halving rounds from 2048
    for (int size = NK; size > KT; size >>= 1) {
        const int half = size >> 1;
        __syncthreads();
        u64 tv[2]; int cnt = 0;
        for (int e = tid; e < half; e += 512) {
            int p = e >> 6, t = e & 63;
            u64 a = skey[p*128 + t], c = skey[p*128 + 64 + t];
            tv[cnt++] = (a > c) ? a : c;
        }
        __syncthreads();
        cnt = 0;
        for (int e = tid; e < half; e += 512) skey[e] = tv[cnt++];
        for (int j = 32; j > 0; j >>= 1) {
            __syncthreads();
            for (int i = tid; i < half; i += 512) {
                const int l = i ^ j;
                if (l > i) {
                    u64 a = skey[i], c = skey[l];
                    bool desc = ((i & KT) == 0);
                    if (desc ? (a < c) : (a > c)) { skey[i] = c; skey[l] = a; }
                }
            }
        }
    }
    __syncthreads();

    if (tid < KT) {
        u64 kk = skey[tid];
        int n = NN - 1 - (int)(kk & 0xFFFu);
        unsigned m = (unsigned)(kk >> 32);
        unsigned u = (m & 0x80000000u) ? (m ^ 0x80000000u) : ~m;
        float s = __uint_as_float(u);
        s_idx[tid] = n; s_t[tid] = tanhf(s); s_v[tid] = s;
    }
    __syncthreads();
    if (tid == 0) {
        float sum = 0.f;
        for (int i = 0; i < KT; ++i) sum += s_v[i];
        out[OFF_POL + b] = sum * (1.f/KT) - s_logZ;
    }

    float* sA = (float*)skey;
    for (int e = tid; e < KT*KT; e += 512) {
        int i = e >> 6, j = e & 63;
        sA[e] = Ahat[(size_t)b*NN*NN + (size_t)s_idx[i]*NN + s_idx[j]];
    }
    __syncthreads();
    if (tid < KT) {
        float s = 0.f;
        for (int i = 0; i < KT; ++i) s += sA[i*KT + tid];
        s_di[tid] = 1.0f / sqrtf(s);
    }
    __syncthreads();
    for (int e = tid; e < KT*KT; e += 512) {
        int i = e >> 6, j = e & 63;
        g_A[b*KT*KT + e] = s_di[j] * sA[e] * s_di[i];
    }

    for (int i = warp; i < DD; i += 16) {
        int k = i & (KT - 1);
        const float* e = node_embs + ((size_t)(b*NN + s_idx[k]))*DD;
        float tv2 = s_t[k];
        for (int d = lane; d < DD; d += 32) {
            float val = e[d];
            g_z[((size_t)b*DD + d)*DD + i] = val * tv2;
            if (i < KT) g_ne[(b*KT + i)*DD + d] = val;
        }
    }
}

// ---------------------------------------------------------------------------
// K4: fused u / rq / preh. 256 thr, 2 rows/warp, k-split x4. grid (32, B).
// ---------------------------------------------------------------------------
__global__ void __launch_bounds__(256) k_gates(
    const float* __restrict__ prevQ,
    const float* __restrict__ Wu, const float* __restrict__ Uu, const float* __restrict__ bu,
    const float* __restrict__ Wr, const float* __restrict__ Ur, const float* __restrict__ br,
    const float* __restrict__ Wh, const float* __restrict__ bh)
{
    extern __shared__ char smraw[];
    u64*    swt = (u64*)smraw;                         // 5*512 u64 (20KB)
    float4* sz  = (float4*)(smraw + 5*512*8);          // 2*512 float4 (16KB)
    float4* sq  = sz + 2*512;                          // 2*512 float4 (16KB)
    const int b = blockIdx.y, i0 = blockIdx.x*4;
    const int tid = threadIdx.x, w = tid>>5, lane = tid&31;
    const int pr = w >> 2, g = w & 3;
    const int rA = pr*2, rB = rA + 1;
    const int giA = i0 + rA, giB = i0 + rB;

    for (int e = tid; e < 512; e += 256) {
        int r = e>>7, k = e&127;
        float a;
        a = Wu[(i0+r)*DD+k]; swt[       e] = pk2(a,a);
        a = Uu[(i0+r)*DD+k]; swt[ 512 + e] = pk2(a,a);
        a = Wr[(i0+r)*DD+k]; swt[1024 + e] = pk2(a,a);
        a = Ur[(i0+r)*DD+k]; swt[1536 + e] = pk2(a,a);
        a = Wh[(i0+r)*DD+k]; swt[2048 + e] = pk2(a,a);
    }
    const float* z = g_z + (size_t)b*DD*DD;
    const float* Q = prevQ + (size_t)b*DD*DD;

    float4 rz[2], rqv[2];
    #pragma unroll
    for (int p = 0; p < 2; ++p) {
        int e = tid + 256*p;
        rz[p]  = ((const float4*)(z + (size_t)(e>>5)*DD))[e&31];
        rqv[p] = ((const float4*)(Q + (size_t)(e>>5)*DD))[e&31];
    }
    #pragma unroll
    for (int p = 0; p < 2; ++p) { int e = tid+256*p; sz[e]=rz[p]; sq[e]=rqv[p]; }
    __syncthreads();

    u64 auA0=0,auA1=0,arA0=0,arA1=0,ahA0=0,ahA1=0;
    u64 auB0=0,auB1=0,arB0=0,arB1=0,ahB0=0,ahB1=0;
    if (g == 0) {
        float4 v;
        v = *(const float4*)&bu[giA*DD + 4*lane]; auA0=pk2(v.x,v.y); auA1=pk2(v.z,v.w);
        v = *(const float4*)&br[giA*DD + 4*lane]; arA0=pk2(v.x,v.y); arA1=pk2(v.z,v.w);
        v = *(const float4*)&bh[giA*DD + 4*lane]; ahA0=pk2(v.x,v.y); ahA1=pk2(v.z,v.w);
        v = *(const float4*)&bu[giB*DD + 4*lane]; auB0=pk2(v.x,v.y); auB1=pk2(v.z,v.w);
        v = *(const float4*)&br[giB*DD + 4*lane]; arB0=pk2(v.x,v.y); arB1=pk2(v.z,v.w);
        v = *(const float4*)&bh[giB*DD + 4*lane]; ahB0=pk2(v.x,v.y); ahB1=pk2(v.z,v.w);
    }

    for (int c = 0; c < 8; ++c) {
        const int cb = c & 1, nb = cb ^ 1;
        if (c < 7) {
            #pragma unroll
            for (int p = 0; p < 2; ++p) {
                int e = tid + 256*p;
                int r16 = (c+1)*16 + (e>>5);
                rz[p]  = ((const float4*)(z + (size_t)r16*DD))[e&31];
                rqv[p] = ((const float4*)(Q + (size_t)r16*DD))[e&31];
            }
        }
        const ulonglong2* zz = (const ulonglong2*)(sz + cb*512);
        const ulonglong2* qq = (const ulonglong2*)(sq + cb*512);
        const int kb = c*16 + g*4;
        const u64* pA = swt + rA*128 + kb;
        const u64* pB = swt + rB*128 + kb;
        #pragma unroll
        for (int q = 0; q < 4; ++q) {
            ulonglong2 zv = zz[(g*4+q)*32 + lane];
            ulonglong2 qv = qq[(g*4+q)*32 + lane];
            u64 wuA=pA[q], uuA=pA[512+q], wrA=pA[1024+q], urA=pA[1536+q], whA=pA[2048+q];
            u64 wuB=pB[q], uuB=pB[512+q], wrB=pB[1024+q], urB=pB[1536+q], whB=pB[2048+q];
            auA0=ffma2(wuA,zv.x,auA0); auA1=ffma2(wuA,zv.y,auA1);
            auA0=ffma2(uuA,qv.x,auA0); auA1=ffma2(uuA,qv.y,auA1);
            arA0=ffma2(wrA,zv.x,arA0); arA1=ffma2(wrA,zv.y,arA1);
            arA0=ffma2(urA,qv.x,arA0); arA1=ffma2(urA,qv.y,arA1);
            ahA0=ffma2(whA,zv.x,ahA0); ahA1=ffma2(whA,zv.y,ahA1);
            auB0=ffma2(wuB,zv.x,auB0); auB1=ffma2(wuB,zv.y,auB1);
            auB0=ffma2(uuB,qv.x,auB0); auB1=ffma2(uuB,qv.y,auB1);
            arB0=ffma2(wrB,zv.x,arB0); arB1=ffma2(wrB,zv.y,arB1);
            arB0=ffma2(urB,qv.x,arB0); arB1=ffma2(urB,qv.y,arB1);
            ahB0=ffma2(whB,zv.x,ahB0); ahB1=ffma2(whB,zv.y,ahB1);
        }
        if (c < 7) {
            #pragma unroll
            for (int p = 0; p < 2; ++p) { int e = tid+256*p; sz[nb*512+e]=rz[p]; sq[nb*512+e]=rqv[p]; }
        }
        __syncthreads();
    }

    u64* sp = (u64*)sz;
    if (g > 0) {
        int base = (pr*36 + (g-1)*12)*32 + lane;
        sp[base+0*32]=auA0;  sp[base+1*32]=auA1;  sp[base+2*32]=arA0;  sp[base+3*32]=arA1;
        sp[base+4*32]=ahA0;  sp[base+5*32]=ahA1;  sp[base+6*32]=auB0;  sp[base+7*32]=auB1;
        sp[base+8*32]=arB0;  sp[base+9*32]=arB1;  sp[base+10*32]=ahB0; sp[base+11*32]=ahB1;
    }
    __syncthreads();
    if (g == 0) {
        #pragma unroll
        for (int gi = 0; gi < 3; ++gi) {
            int base = (pr*36 + gi*12)*32 + lane;
            auA0=padd2(auA0,sp[base+0*32]);  auA1=padd2(auA1,sp[base+1*32]);
            arA0=padd2(arA0,sp[base+2*32]);  arA1=padd2(arA1,sp[base+3*32]);
            ahA0=padd2(ahA0,sp[base+4*32]);  ahA1=padd2(ahA1,sp[base+5*32]);
            auB0=padd2(auB0,sp[base+6*32]);  auB1=padd2(auB1,sp[base+7*32]);
            arB0=padd2(arB0,sp[base+8*32]);  arB1=padd2(arB1,sp[base+9*32]);
            ahB0=padd2(ahB0,sp[base+10*32]); ahB1=padd2(ahB1,sp[base+11*32]);
        }
        float f0,f1,f2,f3;
        {
            const size_t o = ((size_t)b*DD + giA)*DD + 4*lane;
            up2(auA0,f0,f1); up2(auA1,f2,f3);
            *(float4*)&g_u[o] = make_float4(sigf(f0),sigf(f1),sigf(f2),sigf(f3));
            up2(arA0,f0,f1); up2(arA1,f2,f3);
            float4 q4 = *(const float4*)&Q[(size_t)giA*DD + 4*lane];
            *(float4*)&g_rq[o] = make_float4(sigf(f0)*q4.x, sigf(f1)*q4.y, sigf(f2)*q4.z, sigf(f3)*q4.w);
            up2(ahA0,f0,f1); up2(ahA1,f2,f3);
            *(float4*)&g_preh[o] = make_float4(f0,f1,f2,f3);
        }
        {
            const size_t o = ((size_t)b*DD + giB)*DD + 4*lane;
            up2(auB0,f0,f1); up2(auB1,f2,f3);
            *(float4*)&g_u[o] = make_float4(sigf(f0),sigf(f1),sigf(f2),sigf(f3));
            up2(arB0,f0,f1); up2(arB1,f2,f3);
            float4 q4 = *(const float4*)&Q[(size_t)giB*DD + 4*lane];
            *(float4*)&g_rq[o] = make_float4(sigf(f0)*q4.x, sigf(f1)*q4.y, sigf(f2)*q4.z, sigf(f3)*q4.w);
            up2(ahB0,f0,f1); up2(ahB1,f2,f3);
            *(float4*)&g_preh[o] = make_float4(f0,f1,f2,f3);
        }
    }
}

// ---------------------------------------------------------------------------
// K5: newQ. 256 thr, 2 rows/warp, k-split x4. grid (32, B).
// ---------------------------------------------------------------------------
__global__ void __launch_bounds__(256) k_newQ(
    const float* __restrict__ prevQ, const float* __restrict__ Uh)
{
    __shared__ u64 swt[512];
    __shared__ float4 sb[2*512];
    __shared__ u64 sp[2*12*32];
    const int b = blockIdx.y, i0 = blockIdx.x*4;
    const int tid = threadIdx.x, w = tid>>5, lane = tid&31;
    const int pr = w >> 2, g = w & 3;
    const int rA = pr*2, rB = rA + 1;
    const int giA = i0 + rA, giB = i0 + rB;
    for (int e = tid; e < 512; e += 256) {
        float a = Uh[(i0 + (e>>7))*DD + (e&127)]; swt[e] = pk2(a,a);
    }
    const float* Bm = g_rq + (size_t)b*DD*DD;
    float4 rb[2];
    #pragma unroll
    for (int p = 0; p < 2; ++p) { int e = tid+256*p; rb[p] = ((const float4*)(Bm + (size_t)(e>>5)*DD))[e&31]; }
    #pragma unroll
    for (int p = 0; p < 2; ++p) { int e = tid+256*p; sb[e]=rb[p]; }
    __syncthreads();
    u64 aA0=0,aA1=0,aB0=0,aB1=0;
    for (int c = 0; c < 8; ++c) {
        const int cb = c & 1, nb = cb ^ 1;
        if (c < 7) {
            #pragma unroll
            for (int p = 0; p < 2; ++p) {
                int e = tid + 256*p;
                rb[p] = ((const float4*)(Bm + (size_t)((c+1)*16 + (e>>5))*DD))[e&31];
            }
        }
        const ulonglong2* bb = (const ulonglong2*)(sb + cb*512);
        const u64* pA = swt + rA*128 + c*16 + g*4;
        const u64* pB = swt + rB*128 + c*16 + g*4;
        #pragma unroll
        for (int q = 0; q < 4; ++q) {
            ulonglong2 bv = bb[(g*4+q)*32 + lane];
            u64 wtA = pA[q], wtB = pB[q];
            aA0 = ffma2(wtA, bv.x, aA0); aA1 = ffma2(wtA, bv.y, aA1);
            aB0 = ffma2(wtB, bv.x, aB0); aB1 = ffma2(wtB, bv.y, aB1);
        }
        if (c < 7) {
            #pragma unroll
            for (int p = 0; p < 2; ++p) { int e = tid+256*p; sb[nb*512+e]=rb[p]; }
        }
        __syncthreads();
    }
    if (g > 0) {
        int base = (pr*12 + (g-1)*4)*32 + lane;
        sp[base] = aA0; sp[base+32] = aA1; sp[base+64] = aB0; sp[base+96] = aB1;
    }
    __syncthreads();
    if (g == 0) {
        #pragma unroll
        for (int gi = 0; gi < 3; ++gi) {
            int base = (pr*12 + gi*4)*32 + lane;
            aA0 = padd2(aA0, sp[base]);    aA1 = padd2(aA1, sp[base+32]);
            aB0 = padd2(aB0, sp[base+64]); aB1 = padd2(aB1, sp[base+96]);
        }
        float f0,f1,f2,f3;
        {
            up2(aA0,f0,f1); up2(aA1,f2,f3);
            const size_t o = ((size_t)b*DD + giA)*DD + 4*lane;
            float4 ph = *(const float4*)&g_preh[o];
            float4 uv = *(const float4*)&g_u[o];
            float4 q4 = *(const float4*)&prevQ[(size_t)b*DD*DD + giA*DD + 4*lane];
            float h0 = tanhf(f0+ph.x), h1 = tanhf(f1+ph.y), h2 = tanhf(f2+ph.z), h3 = tanhf(f3+ph.w);
            *(float4*)&g_newQ[o] = make_float4(
                (1.f-uv.x)*q4.x + uv.x*h0, (1.f-uv.y)*q4.y + uv.y*h1,
                (1.f-uv.z)*q4.z + uv.z*h2, (1.f-uv.w)*q4.w + uv.w*h3);
        }
        {
            up2(aB0,f0,f1); up2(aB1,f2,f3);
            const size_t o = ((size_t)b*DD + giB)*DD + 4*lane;
            float4 ph = *(const float4*)&g_preh[o];
            float4 uv = *(const float4*)&g_u[o];
            float4 q4 = *(const float4*)&prevQ[(size_t)b*DD*DD + giB*DD + 4*lane];
            float h0 = tanhf(f0+ph.x), h1 = tanhf(f1+ph.y), h2 = tanhf(f2+ph.z), h3 = tanhf(f3+ph.w);
            *(float4*)&g_newQ[o] = make_float4(
                (1.f-uv.x)*q4.x + uv.x*h0, (1.f-uv.y)*q4.y + uv.y*h1,
                (1.f-uv.z)*q4.z + uv.z*h2, (1.f-uv.w)*q4.w + uv.w*h3);
        }
    }
}

// ---------------------------------------------------------------------------
// K6: P = ne @ newQ. 256 thr, 2 rows/warp, k-split x4. grid (16, B).
// ---------------------------------------------------------------------------
__global__ void __launch_bounds__(256) k_g1()
{
    __shared__ u64 swt[512];
    __shared__ float4 sb[2*512];
    __shared__ u64 sp[2*12*32];
    const int b = blockIdx.y, i0 = blockIdx.x*4;
    const int tid = threadIdx.x, w = tid>>5, lane = tid&31;
    const int pr = w >> 2, g = w & 3;
    const int rA = pr*2, rB = rA + 1;
    const int giA = i0 + rA, giB = i0 + rB;
    for (int e = tid; e < 512; e += 256) {
        float a = g_ne[((size_t)b*KT + i0 + (e>>7))*DD + (e&127)]; swt[e] = pk2(a,a);
    }
    const float* Bm = g_newQ + (size_t)b*DD*DD;
    float4 rb[2];
    #pragma unroll
    for (int p = 0; p < 2; ++p) { int e = tid+256*p; rb[p] = ((const float4*)(Bm + (size_t)(e>>5)*DD))[e&31]; }
    #pragma unroll
    for (int p = 0; p < 2; ++p) { int e = tid+256*p; sb[e]=rb[p]; }
    __syncthreads();
    u64 aA0=0,aA1=0,aB0=0,aB1=0;
    for (int c = 0; c < 8; ++c) {
        const int cb = c & 1, nb = cb ^ 1;
        if (c < 7) {
            #pragma unroll
            for (int p = 0; p < 2; ++p) {
                int e = tid + 256*p;
                rb[p] = ((const float4*)(Bm + (size_t)((c+1)*16 + (e>>5))*DD))[e&31];
            }
        }
        const ulonglong2* bb = (const ulonglong2*)(sb + cb*512);
        const u64* pA = swt + rA*128 + c*16 + g*4;
        const u64* pB = swt + rB*128 + c*16 + g*4;
        #pragma unroll
        for (int q = 0; q < 4; ++q) {
            ulonglong2 bv = bb[(g*4+q)*32 + lane];
            u64 wtA = pA[q], wtB = pB[q];
            aA0 = ffma2(wtA, bv.x, aA0); aA1 = ffma2(wtA, bv.y, aA1);
            aB0 = ffma2(wtB, bv.x, aB0); aB1 = ffma2(wtB, bv.y, aB1);
        }
        if (c < 7) {
            #pragma unroll
            for (int p = 0; p < 2; ++p) { int e = tid+256*p; sb[nb*512+e]=rb[p]; }
        }
        __syncthreads();
    }
    if (g > 0) {
        int base = (pr*12 + (g-1)*4)*32 + lane;
        sp[base] = aA0; sp[base+32] = aA1; sp[base+64] = aB0; sp[base+96] = aB1;
    }
    __syncthreads();
    if (g == 0) {
        #pragma unroll
        for (int gi = 0; gi < 3; ++gi) {
            int base = (pr*12 + gi*4)*32 + lane;
            aA0 = padd2(aA0, sp[base]);    aA1 = padd2(aA1, sp[base+32]);
            aB0 = padd2(aB0, sp[base+64]); aB1 = padd2(aB1, sp[base+96]);
        }
        float f0,f1,f2,f3;
        up2(aA0,f0,f1); up2(aA1,f2,f3);
        *(float4*)&g_P[((size_t)b*KT + giA)*DD + 4*lane] = make_float4(f0,f1,f2,f3);
        up2(aB0,f0,f1); up2(aB1,f2,f3);
        *(float4*)&g_P[((size_t)b*KT + giB)*DD + 4*lane] = make_float4(f0,f1,f2,f3);
    }
}

// ---------------------------------------------------------------------------
// K7: h1 = relu(A@P); G = h1@staticW. 256 thr, 2 rows/warp, k-split x4.
// grid (16, B).
// ---------------------------------------------------------------------------
__global__ void __launch_bounds__(256) k_g23(const float* __restrict__ sW)
{
    __shared__ u64 sAW[4*KT];
    __shared__ u64 sh1p[4*DD];
    __shared__ float buf[KT*DD];
    __shared__ u64 sp[2*12*32];
    const int b = blockIdx.y, i0 = blockIdx.x*4;
    const int tid = threadIdx.x, w = tid>>5, lane = tid&31;
    const int pr = w >> 2, g = w & 3;
    const int rA = pr*2, rB = rA + 1;
    const int giA = i0 + rA, giB = i0 + rB;
    for (int e = tid; e < 4*KT; e += 256) {
        float a = g_A[b*KT*KT + (i0 + (e>>6))*KT + (e&63)]; sAW[e] = pk2(a,a);
    }
    float4* bf4 = (float4*)buf;
    const float4* Psrc = (const float4*)(g_P + (size_t)b*KT*DD);
    for (int e = tid; e < 2048; e += 256) bf4[e] = Psrc[e];
    __syncthreads();

    u64 aA0=0,aA1=0,aB0=0,aB1=0;
    {
        const ulonglong2* bb = (const ulonglong2*)buf;
        const u64* pA = sAW + rA*KT + g*16;
        const u64* pB = sAW + rB*KT + g*16;
        #pragma unroll
        for (int q = 0; q < 16; ++q) {
            ulonglong2 bv = bb[(g*16+q)*32 + lane];
            u64 wtA = pA[q], wtB = pB[q];
            aA0 = ffma2(wtA, bv.x, aA0); aA1 = ffma2(wtA, bv.y, aA1);
            aB0 = ffma2(wtB, bv.x, aB0); aB1 = ffma2(wtB, bv.y, aB1);
        }
    }
    __syncthreads();
    if (g > 0) {
        int base = (pr*12 + (g-1)*4)*32 + lane;
        sp[base] = aA0; sp[base+32] = aA1; sp[base+64] = aB0; sp[base+96] = aB1;
    }
    __syncthreads();
    if (g == 0) {
        #pragma unroll
        for (int gi = 0; gi < 3; ++gi) {
            int base = (pr*12 + gi*4)*32 + lane;
            aA0 = padd2(aA0, sp[base]);    aA1 = padd2(aA1, sp[base+32]);
            aB0 = padd2(aB0, sp[base+64]); aB1 = padd2(aB1, sp[base+96]);
        }
        float f0,f1,f2,f3;
        up2(aA0,f0,f1); up2(aA1,f2,f3);
        f0=fmaxf(f0,0.f); f1=fmaxf(f1,0.f); f2=fmaxf(f2,0.f); f3=fmaxf(f3,0.f);
        *(float4*)&g_h1[((size_t)b*KT + giA)*DD + 4*lane] = make_float4(f0,f1,f2,f3);
        sh1p[rA*DD + 4*lane+0]=pk2(f0,f0); sh1p[rA*DD + 4*lane+1]=pk2(f1,f1);
        sh1p[rA*DD + 4*lane+2]=pk2(f2,f2); sh1p[rA*DD + 4*lane+3]=pk2(f3,f3);
        up2(aB0,f0,f1); up2(aB1,f2,f3);
        f0=fmaxf(f0,0.f); f1=fmaxf(f1,0.f); f2=fmaxf(f2,0.f); f3=fmaxf(f3,0.f);
        *(float4*)&g_h1[((size_t)b*KT + giB)*DD + 4*lane] = make_float4(f0,f1,f2,f3);
        sh1p[rB*DD + 4*lane+0]=pk2(f0,f0); sh1p[rB*DD + 4*lane+1]=pk2(f1,f1);
        sh1p[rB*DD + 4*lane+2]=pk2(f2,f2); sh1p[rB*DD + 4*lane+3]=pk2(f3,f3);
    }
    __syncthreads();

    float4 rb[4];
    #pragma unroll
    for (int p = 0; p < 4; ++p) {
        int e = tid + 256*p;
        rb[p] = ((const float4*)(sW + (size_t)(e>>5)*DD))[e&31];
    }
    #pragma unroll
    for (int p = 0; p < 4; ++p) { int e = tid+256*p; bf4[e] = rb[p]; }
    __syncthreads();
    u64 gA0=0,gA1=0,gB0=0,gB1=0;
    for (int c = 0; c < 4; ++c) {
        const int cb = c & 1, nb = cb ^ 1;
        if (c < 3) {
            #pragma unroll
            for (int p = 0; p < 4; ++p) {
                int e = tid + 256*p;
                rb[p] = ((const float4*)(sW + (size_t)((c+1)*32 + (e>>5))*DD))[e&31];
            }
        }
        const ulonglong2* bb = (const ulonglong2*)(buf + cb*4096);
        const u64* hA = sh1p + rA*DD + c*32 + g*8;
        const u64* hB = sh1p + rB*DD + c*32 + g*8;
        #pragma unroll
        for (int q = 0; q < 8; ++q) {
            ulonglong2 bv = bb[(g*8+q)*32 + lane];
            u64 wtA = hA[q], wtB = hB[q];
            gA0 = ffma2(wtA, bv.x, gA0); gA1 = ffma2(wtA, bv.y, gA1);
            gB0 = ffma2(wtB, bv.x, gB0); gB1 = ffma2(wtB, bv.y, gB1);
        }
        if (c < 3) {
            #pragma unroll
            for (int p = 0; p < 4; ++p) { int e = tid+256*p; bf4[nb*1024 + e] = rb[p]; }
        }
        __syncthreads();
    }
    if (g > 0) {
        int base = (pr*12 + (g-1)*4)*32 + lane;
        sp[base] = gA0; sp[base+32] = gA1; sp[base+64] = gB0; sp[base+96] = gB1;
    }
    __syncthreads();
    if (g == 0) {
        #pragma unroll
        for (int gi = 0; gi < 3; ++gi) {
            int base = (pr*12 + gi*4)*32 + lane;
            gA0 = padd2(gA0, sp[base]);    gA1 = padd2(gA1, sp[base+32]);
            gB0 = padd2(gB0, sp[base+64]); gB1 = padd2(gB1, sp[base+96]);
        }
        float f0,f1,f2,f3;
        up2(gA0,f0,f1); up2(gA1,f2,f3);
        *(float4*)&g_G[((size_t)b*KT + giA)*DD + 4*lane] = make_float4(f0,f1,f2,f3);
        up2(gB0,f0,f1); up2(gB1,f2,f3);
        *(float4*)&g_G[((size_t)b*KT + giB)*DD + 4*lane] = make_float4(f0,f1,f2,f3);
    }
}

// ---------------------------------------------------------------------------
// K8: out = (h1 + relu(A @ G)) / 2. 256 thr, 2 rows/warp, k-split x4.
// ---------------------------------------------------------------------------
__global__ void __launch_bounds__(256) k_g4(float* __restrict__ out)
{
    __shared__ u64 sAW[4*KT];
    __shared__ float buf[KT*DD];
    __shared__ u64 sp[2*12*32];
    const int b = blockIdx.y, i0 = blockIdx.x*4;
    const int tid = threadIdx.x, w = tid>>5, lane = tid&31;
    const int pr = w >> 2, g = w & 3;
    const int rA = pr*2, rB = rA + 1;
    const int giA = i0 + rA, giB = i0 + rB;
    for (int e = tid; e < 4*KT; e += 256) {
        float a = g_A[b*KT*KT + (i0 + (e>>6))*KT + (e&63)]; sAW[e] = pk2(a,a);
    }
    float4* bf4 = (float4*)buf;
    const float4* Gsrc = (const float4*)(g_G + (size_t)b*KT*DD);
    for (int e = tid; e < 2048; e += 256) bf4[e] = Gsrc[e];
    __syncthreads();
    u64 aA0=0,aA1=0,aB0=0,aB1=0;
    const ulonglong2* bb = (const ulonglong2*)buf;
    const u64* pA = sAW + rA*KT + g*16;
    const u64* pB = sAW + rB*KT + g*16;
    #pragma unroll
    for (int q = 0; q < 16; ++q) {
        ulonglong2 bv = bb[(g*16+q)*32 + lane];
        u64 wtA = pA[q], wtB = pB[q];
        aA0 = ffma2(wtA, bv.x, aA0); aA1 = ffma2(wtA, bv.y, aA1);
        aB0 = ffma2(wtB, bv.x, aB0); aB1 = ffma2(wtB, bv.y, aB1);
    }
    if (g > 0) {
        int base = (pr*12 + (g-1)*4)*32 + lane;
        sp[base] = aA0; sp[base+32] = aA1; sp[base+64] = aB0; sp[base+96] = aB1;
    }
    __syncthreads();
    if (g == 0) {
        #pragma unroll
        for (int gi = 0; gi < 3; ++gi) {
            int base = (pr*12 + gi*4)*32 + lane;
            aA0 = padd2(aA0, sp[base]);    aA1 = padd2(aA1, sp[base+32]);
            aB0 = padd2(aB0, sp[base+64]); aB1 = padd2(aB1, sp[base+96]);
        }
        float f0,f1,f2,f3;
        up2(aA0,f0,f1); up2(aA1,f2,f3);
        {
            float4 h1v = *(const float4*)&g_h1[((size_t)b*KT + giA)*DD + 4*lane];
            *(float4*)&out[((size_t)b*KT + giA)*DD + 4*lane] = make_float4(
                (h1v.x + fmaxf(f0,0.f))*0.5f, (h1v.y + fmaxf(f1,0.f))*0.5f,
                (h1v.z + fmaxf(f2,0.f))*0.5f, (h1v.w + fmaxf(f3,0.f))*0.5f);
        }
        up2(aB0,f0,f1); up2(aB1,f2,f3);
        {
            float4 h1v = *(const float4*)&g_h1[((size_t)b*KT + giB)*DD + 4*lane];
            *(float4*)&out[((size_t)b*KT + giB)*DD + 4*lane] = make_float4(
                (h1v.x + fmaxf(f0,0.f))*0.5f, (h1v.y + fmaxf(f1,0.f))*0.5f,
                (h1v.z + fmaxf(f2,0.f))*0.5f, (h1v.w + fmaxf(f3,0.f))*0.5f);
        }
    }
}

// ---------------------------------------------------------------------------
extern "C" void kernel_launch(void* const* d_in, const int* in_sizes, int n_in,
                              void* d_out, int out_size)
{
    const float* Ahat      = (const float*)d_in[0];
    const float* node_embs = (const float*)d_in[1];
    const float* ht        = (const float*)d_in[3];
    const float* prevQ     = (const float*)d_in[4];
    const float* W_map     = (const float*)d_in[5];
    const float* b_map     = (const float*)d_in[6];
    const float* Wu        = (const float*)d_in[7];
    const float* Uu        = (const float*)d_in[8];
    const float* bu        = (const float*)d_in[9];
    const float* Wr        = (const float*)d_in[10];
    const float* Ur        = (const float*)d_in[11];
    const float* br        = (const float*)d_in[12];
    const float* Wh        = (const float*)d_in[13];
    const float* Uh        = (const float*)d_in[14];
    const float* bh        = (const float*)d_in[15];
    const float* sW        = (const float*)d_in[16];
    float* out = (float*)d_out;

    const int gates_smem = 5*512*8 + 2*512*16 + 2*512*16;   // 53248 B
    cudaFuncSetAttribute(k_gates, cudaFuncAttributeMaxDynamicSharedMemorySize, gates_smem);

    k_scorer<<<BB, 512>>>(ht, W_map, b_map, out);
    k_scores<<<dim3(32, BB), 128>>>(node_embs);
    k_topk_gather<<<BB, 512, KT*KT*(int)sizeof(float)>>>(node_embs, Ahat, out);
    k_gates<<<dim3(32, BB), 256, gates_smem>>>(prevQ, Wu, Uu, bu, Wr, Ur, br, Wh, bh);
    k_newQ<<<dim3(32, BB), 256>>>(prevQ, Uh);
    k_g1<<<dim3(16, BB), 256>>>();
    k_g23<<<dim3(16, BB), 256>>>(sW);
    k_g4<<<dim3(16, BB), 256>>>(out);
}